// round 17
// baseline (speedup 1.0000x reference)
#include <cuda_runtime.h>
#include <cstdint>

// GRU_12962211299468 : B=65536, T=9, I=57, H=2, O=1, fp32
// Round 17: ONE launch, two roles by blockIdx:
//   bids 0..4607   : K1 projection CTAs (R14's proven cp.async + FFMA2 path)
//   bids 4608..5119: K2 recurrence CTAs, each spin-waits (acquire) on a flag
//                    until its 9 producer K1 CTAs signal (release).
// Launch-order safety: all K1 bids < all K2 bids -> every K1 CTA dispatches
// before any K2 CTA is resident; K1 has no dependencies -> no deadlock.
// K2 overlaps K1's tail AND reads gx while it is still L2-resident.

#define T_STEPS 9
#define I_DIM   57
#define B_TOT   65536
#define NROWS_T (B_TOT * T_STEPS)       // 589824 rows
#define RPW     32                      // rows per warp
#define RPW_FLT (RPW * I_DIM)           // 1824 floats per warp tile
#define RPW_V4  (RPW_FLT / 4)           // 456 chunks
#define CWARPS  4
#define NTHR    (CWARPS * 32)           // 128
#define K1_CTAS (NROWS_T / RPW / CWARPS)    // 4608
#define K2_CTAS (B_TOT / 128)               // 512
#define GRID    (K1_CTAS + K2_CTAS)         // 5120
#define NCHUNK  14                      // gate chunks
#define B4      (B_TOT * 4)
#define PROW    120                     // packed-weight row: 60 pairs

__device__ __align__(16) float g_gx[(size_t)NCHUNK * B4];   // 14.7 MB
__device__ int g_done[K2_CTAS];                              // producer counters

typedef unsigned long long u64;

__device__ __forceinline__ uint32_t s2u(const void* p) {
    uint32_t a;
    asm("{ .reg .u64 t; cvta.to.shared.u64 t, %1; cvt.u32.u64 %0, t; }"
        : "=r"(a) : "l"(p));
    return a;
}
__device__ __forceinline__ void cp16(uint32_t dst, const void* src) {
    asm volatile("cp.async.cg.shared.global [%0], [%1], 16;"
                 :: "r"(dst), "l"(src) : "memory");
}
__device__ __forceinline__ void cp_commit_wait0() {
    asm volatile("cp.async.commit_group;" ::: "memory");
    asm volatile("cp.async.wait_group 0;" ::: "memory");
}
__device__ __forceinline__ u64 pack2(float lo, float hi) {
    u64 r;
    asm("mov.b64 %0, {%1, %2};" : "=l"(r) : "f"(lo), "f"(hi));
    return r;
}
__device__ __forceinline__ void unpack2(float& lo, float& hi, u64 v) {
    asm("mov.b64 {%0, %1}, %2;" : "=f"(lo), "=f"(hi) : "l"(v));
}
__device__ __forceinline__ void fma2(u64& d, u64 a, u64 b) {
    asm("fma.rn.f32x2 %0, %1, %2, %0;" : "+l"(d) : "l"(a), "l"(b));
}

__device__ __forceinline__ float sigf(float v) {
    return 1.0f / (1.0f + __expf(-v));
}
__device__ __forceinline__ float tanh_ex(float v) {
    return 1.0f - 2.0f / (__expf(2.0f * v) + 1.0f);
}

__global__ __launch_bounds__(NTHR, 7) void gru_all(
    const float* __restrict__ x,
    const float* __restrict__ Wih,   // [6,57]
    const float* __restrict__ Whh,   // [6,2]
    const float* __restrict__ bih,   // [6]
    const float* __restrict__ bhh,   // [6]
    const float* __restrict__ fcw,   // [2]
    const float* __restrict__ fcb,   // [1]
    float* __restrict__ out)         // [B]
{
    const int bid = blockIdx.x;
    const int tid = threadIdx.x;

    if (bid < K1_CTAS) {
        // ================= K1 role: projection =================
        __shared__ __align__(16) float sx[CWARPS][RPW_FLT];
        __shared__ __align__(16) float swp[3 * PROW];

        const int wid  = tid >> 5;
        const int lane = tid & 31;
        const int wg   = bid * CWARPS + wid;

        // stage warp tile via cp.async
        {
            const float4* src = reinterpret_cast<const float4*>(x) +
                                (size_t)wg * RPW_V4;
            const uint32_t sb = s2u(&sx[wid][0]);
#pragma unroll
            for (int k = 0; k < 15; ++k) {
                int j = lane + 32 * k;
                if (j < RPW_V4) cp16(sb + 16u * (uint32_t)j, src + j);
            }
        }

        // pack W_ih pairwise into smem (overlaps copies)
        for (int j = tid; j < 3 * (PROW / 2); j += NTHR) {
            int p = j / (PROW / 2);
            int i = j - p * (PROW / 2);
            float a = 0.0f, b = 0.0f;
            if (i < I_DIM) {
                a = Wih[(2 * p) * I_DIM + i];
                b = Wih[(2 * p + 1) * I_DIM + i];
            }
            swp[p * PROW + 2 * i]     = a;
            swp[p * PROW + 2 * i + 1] = b;
        }
        __syncthreads();

        const u64 bi01 = pack2(bih[0], bih[1]);
        const u64 bi23 = pack2(bih[2], bih[3]);
        const u64 bi45 = pack2(bih[4], bih[5]);

        cp_commit_wait0();
        __syncwarp();

        const float* row = &sx[wid][lane * I_DIM];   // stride 57: conflict-free

        u64 a01 = bi01, a23 = bi23, a45 = bi45;
#pragma unroll
        for (int c = 0; c < 14; ++c) {
            float x0 = row[4 * c + 0];
            float x1 = row[4 * c + 1];
            float x2 = row[4 * c + 2];
            float x3 = row[4 * c + 3];
            u64 xx0 = pack2(x0, x0);
            u64 xx1 = pack2(x1, x1);
            u64 xx2 = pack2(x2, x2);
            u64 xx3 = pack2(x3, x3);
            {
                const float4* wp = reinterpret_cast<const float4*>(&swp[0 * PROW + 8 * c]);
                float4 wa = wp[0], wb = wp[1];
                fma2(a01, pack2(wa.x, wa.y), xx0);
                fma2(a01, pack2(wa.z, wa.w), xx1);
                fma2(a01, pack2(wb.x, wb.y), xx2);
                fma2(a01, pack2(wb.z, wb.w), xx3);
            }
            {
                const float4* wp = reinterpret_cast<const float4*>(&swp[1 * PROW + 8 * c]);
                float4 wa = wp[0], wb = wp[1];
                fma2(a23, pack2(wa.x, wa.y), xx0);
                fma2(a23, pack2(wa.z, wa.w), xx1);
                fma2(a23, pack2(wb.x, wb.y), xx2);
                fma2(a23, pack2(wb.z, wb.w), xx3);
            }
            {
                const float4* wp = reinterpret_cast<const float4*>(&swp[2 * PROW + 8 * c]);
                float4 wa = wp[0], wb = wp[1];
                fma2(a45, pack2(wa.x, wa.y), xx0);
                fma2(a45, pack2(wa.z, wa.w), xx1);
                fma2(a45, pack2(wb.x, wb.y), xx2);
                fma2(a45, pack2(wb.z, wb.w), xx3);
            }
        }
        {
            float xs = row[56];
            u64 xx = pack2(xs, xs);
            fma2(a01, *reinterpret_cast<const u64*>(&swp[0 * PROW + 112]), xx);
            fma2(a23, *reinterpret_cast<const u64*>(&swp[1 * PROW + 112]), xx);
            fma2(a45, *reinterpret_cast<const u64*>(&swp[2 * PROW + 112]), xx);
        }

        float g0, g1, g2, g3, g4, g5;
        unpack2(g0, g1, a01);
        unpack2(g2, g3, a23);
        unpack2(g4, g5, a45);

        // scatter to chunk-interleaved gx
        const int r = wg * RPW + lane;             // global row = 9b + t
        const int b = r / 9;
        const int t = r - 9 * b;
        const int c0 = (6 * t) >> 2;
        float* base = &g_gx[(size_t)c0 * B4 + b * 4];
        if ((t & 1) == 0) {
            *reinterpret_cast<float4*>(base) = make_float4(g0, g1, g2, g3);
            *reinterpret_cast<float2*>(base + B4) = make_float2(g4, g5);
        } else {
            *reinterpret_cast<float2*>(base + 2) = make_float2(g0, g1);
            *reinterpret_cast<float4*>(base + B4) = make_float4(g2, g3, g4, g5);
        }

        // signal: this CTA's 512 rows belong entirely to K2 chunk bid/9
        __syncthreads();
        if (tid == 0) {
            __threadfence();                       // release gx stores
            atomicAdd(&g_done[bid / 9], 1);
        }
    } else {
        // ================= K2 role: recurrence =================
        const int k = bid - K1_CTAS;               // chunk id, 0..511
        const int b = k * 128 + tid;               // batch element

        // spin until all 9 producer CTAs signalled
        if (tid == 0) {
            volatile int* f = &g_done[k];
            while (*f < 9) __nanosleep(200);
        }
        __syncthreads();
        __threadfence();                           // acquire

        float v[NCHUNK * 4];
#pragma unroll
        for (int c = 0; c < NCHUNK; ++c)
            reinterpret_cast<float4*>(v)[c] =
                *reinterpret_cast<const float4*>(&g_gx[(size_t)c * B4 + b * 4]);

        const float w00 = __ldg(Whh + 0),  w01 = __ldg(Whh + 1);
        const float w10 = __ldg(Whh + 2),  w11 = __ldg(Whh + 3);
        const float w20 = __ldg(Whh + 4),  w21 = __ldg(Whh + 5);
        const float w30 = __ldg(Whh + 6),  w31 = __ldg(Whh + 7);
        const float w40 = __ldg(Whh + 8),  w41 = __ldg(Whh + 9);
        const float w50 = __ldg(Whh + 10), w51 = __ldg(Whh + 11);
        const float bh0 = __ldg(bhh + 0), bh1 = __ldg(bhh + 1), bh2 = __ldg(bhh + 2);
        const float bh3 = __ldg(bhh + 3), bh4 = __ldg(bhh + 4), bh5 = __ldg(bhh + 5);

        float h0 = 0.0f, h1 = 0.0f;
#pragma unroll
        for (int t = 0; t < T_STEPS; ++t) {
            float q0 = v[6 * t + 0];
            float q1 = v[6 * t + 1];
            float q2 = v[6 * t + 2];
            float q3 = v[6 * t + 3];
            float q4 = v[6 * t + 4];
            float q5 = v[6 * t + 5];

            float a0 = w00 * h0 + w01 * h1 + bh0;
            float a1 = w10 * h0 + w11 * h1 + bh1;
            float a2 = w20 * h0 + w21 * h1 + bh2;
            float a3 = w30 * h0 + w31 * h1 + bh3;
            float a4 = w40 * h0 + w41 * h1 + bh4;
            float a5 = w50 * h0 + w51 * h1 + bh5;

            float r0 = sigf(q0 + a0);
            float r1 = sigf(q1 + a1);
            float z0 = sigf(q2 + a2);
            float z1 = sigf(q3 + a3);
            float n0 = tanh_ex(q4 + r0 * a4);
            float n1 = tanh_ex(q5 + r1 * a5);

            h0 = (1.0f - z0) * n0 + z0 * h0;
            h1 = (1.0f - z1) * n1 + z1 * h1;
        }

        out[b] = __ldg(fcw + 0) * h0 + __ldg(fcw + 1) * h1 + __ldg(fcb);
    }
}

extern "C" void kernel_launch(void* const* d_in, const int* in_sizes, int n_in,
                              void* d_out, int out_size) {
    const float* x   = (const float*)d_in[0];
    const float* Wih = (const float*)d_in[1];
    const float* Whh = (const float*)d_in[2];
    const float* bih = (const float*)d_in[3];
    const float* bhh = (const float*)d_in[4];
    const float* fcw = (const float*)d_in[5];
    const float* fcb = (const float*)d_in[6];
    float* out = (float*)d_out;

    (void)in_sizes; (void)n_in; (void)out_size;

    static void* done_addr = nullptr;
    if (!done_addr) cudaGetSymbolAddress(&done_addr, g_done);

    // reset producer counters (async memset: graph-capturable, no alloc)
    cudaMemsetAsync(done_addr, 0, K2_CTAS * sizeof(int), 0);

    gru_all<<<GRID, NTHR>>>(x, Wih, Whh, bih, bhh, fcw, fcb, out);
}